// round 7
// baseline (speedup 1.0000x reference)
#include <cuda_runtime.h>
#include <cstdint>

#define NT 16     // NUM_TYPES
#define OD 128    // OUT_DIM
#define N_MAX 100000

// Scratch (allocation-free rule: __device__ globals). 16B-aligned for float4.
__device__ __align__(16) float g_p[N_MAX * NT];
__device__ __align__(16) float g_msum[N_MAX * NT];
__device__ int g_idx64;   // 1 if indices are int64, 0 if int32

// ---------------------------------------------------------------------------
// Detect index width. int32 data misread as int64 gives values >= 2^32 with
// overwhelming probability (hi half would be a random node id, rarely 0).
// ---------------------------------------------------------------------------
__global__ void k_detect(const void* __restrict__ src, int E) {
    if (blockIdx.x == 0 && threadIdx.x == 0) {
        const unsigned long long* p = (const unsigned long long*)src;
        int is64 = 1;
        int lim = (E / 2 < 16) ? E / 2 : 16;
        for (int i = 0; i < lim; i++) {
            if (p[i] > 0x7FFFFFFFULL) is64 = 0;
        }
        g_idx64 = is64;
    }
}

// ---------------------------------------------------------------------------
// Zero msum
// ---------------------------------------------------------------------------
__global__ void k_zero(int n) {
    int i = blockIdx.x * blockDim.x + threadIdx.x;
    if (i < n * NT) g_msum[i] = 0.0f;
}

// ---------------------------------------------------------------------------
// p = softmax(relu(r@W1+b1) @ Wp + bp)   TWO nodes per thread
// W1: [16,128] row-major, Wp: [128,16] row-major.
// All shared-weight loads are uniform-address (warp broadcast, conflict-free).
// ---------------------------------------------------------------------------
__global__ void __launch_bounds__(128) k_compute_p(
        const float* __restrict__ r,
        const float* __restrict__ W1,
        const float* __restrict__ b1,
        const float* __restrict__ Wp,
        const float* __restrict__ bp,
        int n) {
    __shared__ float sW1t[OD * NT];  // [j*16 + k] = W1[k*128 + j]
    __shared__ float sWp [OD * NT];  // [j*16 + t] = Wp[j*16 + t]
    __shared__ float sb1 [OD];
    __shared__ float sbp [NT];

    for (int i = threadIdx.x; i < OD * NT; i += blockDim.x) {
        int j = i >> 4, k = i & 15;
        sW1t[i] = W1[k * OD + j];
        sWp[i]  = Wp[i];
    }
    for (int i = threadIdx.x; i < OD; i += blockDim.x) sb1[i] = b1[i];
    if (threadIdx.x < NT) sbp[threadIdx.x] = bp[threadIdx.x];
    __syncthreads();

    int node0 = (blockIdx.x * blockDim.x + threadIdx.x) * 2;
    if (node0 >= n) return;
    bool two = (node0 + 1 < n);

    const float4* rp0 = (const float4*)(r + (size_t)node0 * NT);
    float4 a0 = rp0[0], a1 = rp0[1], a2 = rp0[2], a3 = rp0[3];
    float4 b0, b1v, b2, b3;
    if (two) {
        const float4* rp1 = (const float4*)(r + (size_t)(node0 + 1) * NT);
        b0 = rp1[0]; b1v = rp1[1]; b2 = rp1[2]; b3 = rp1[3];
    } else {
        b0 = b1v = b2 = b3 = make_float4(0.f, 0.f, 0.f, 0.f);
    }

    float accA[NT], accB[NT];
#pragma unroll
    for (int t = 0; t < NT; t++) { accA[t] = sbp[t]; accB[t] = sbp[t]; }

    const float4* w1t4 = (const float4*)sW1t;
    const float4* wp4  = (const float4*)sWp;

#pragma unroll 2
    for (int j = 0; j < OD; j++) {
        float4 wa = w1t4[j * 4 + 0];
        float4 wb = w1t4[j * 4 + 1];
        float4 wc = w1t4[j * 4 + 2];
        float4 wd = w1t4[j * 4 + 3];
        float bj = sb1[j];

        float zA = bj, zB = bj;
        zA = fmaf(a0.x, wa.x, zA); zA = fmaf(a0.y, wa.y, zA);
        zA = fmaf(a0.z, wa.z, zA); zA = fmaf(a0.w, wa.w, zA);
        zA = fmaf(a1.x, wb.x, zA); zA = fmaf(a1.y, wb.y, zA);
        zA = fmaf(a1.z, wb.z, zA); zA = fmaf(a1.w, wb.w, zA);
        zA = fmaf(a2.x, wc.x, zA); zA = fmaf(a2.y, wc.y, zA);
        zA = fmaf(a2.z, wc.z, zA); zA = fmaf(a2.w, wc.w, zA);
        zA = fmaf(a3.x, wd.x, zA); zA = fmaf(a3.y, wd.y, zA);
        zA = fmaf(a3.z, wd.z, zA); zA = fmaf(a3.w, wd.w, zA);
        zA = fmaxf(zA, 0.0f);

        zB = fmaf(b0.x, wa.x, zB); zB = fmaf(b0.y, wa.y, zB);
        zB = fmaf(b0.z, wa.z, zB); zB = fmaf(b0.w, wa.w, zB);
        zB = fmaf(b1v.x, wb.x, zB); zB = fmaf(b1v.y, wb.y, zB);
        zB = fmaf(b1v.z, wb.z, zB); zB = fmaf(b1v.w, wb.w, zB);
        zB = fmaf(b2.x, wc.x, zB); zB = fmaf(b2.y, wc.y, zB);
        zB = fmaf(b2.z, wc.z, zB); zB = fmaf(b2.w, wc.w, zB);
        zB = fmaf(b3.x, wd.x, zB); zB = fmaf(b3.y, wd.y, zB);
        zB = fmaf(b3.z, wd.z, zB); zB = fmaf(b3.w, wd.w, zB);
        zB = fmaxf(zB, 0.0f);

        float4 p0 = wp4[j * 4 + 0];
        float4 p1 = wp4[j * 4 + 1];
        float4 p2 = wp4[j * 4 + 2];
        float4 p3 = wp4[j * 4 + 3];
        accA[0]  = fmaf(zA, p0.x, accA[0]);  accB[0]  = fmaf(zB, p0.x, accB[0]);
        accA[1]  = fmaf(zA, p0.y, accA[1]);  accB[1]  = fmaf(zB, p0.y, accB[1]);
        accA[2]  = fmaf(zA, p0.z, accA[2]);  accB[2]  = fmaf(zB, p0.z, accB[2]);
        accA[3]  = fmaf(zA, p0.w, accA[3]);  accB[3]  = fmaf(zB, p0.w, accB[3]);
        accA[4]  = fmaf(zA, p1.x, accA[4]);  accB[4]  = fmaf(zB, p1.x, accB[4]);
        accA[5]  = fmaf(zA, p1.y, accA[5]);  accB[5]  = fmaf(zB, p1.y, accB[5]);
        accA[6]  = fmaf(zA, p1.z, accA[6]);  accB[6]  = fmaf(zB, p1.z, accB[6]);
        accA[7]  = fmaf(zA, p1.w, accA[7]);  accB[7]  = fmaf(zB, p1.w, accB[7]);
        accA[8]  = fmaf(zA, p2.x, accA[8]);  accB[8]  = fmaf(zB, p2.x, accB[8]);
        accA[9]  = fmaf(zA, p2.y, accA[9]);  accB[9]  = fmaf(zB, p2.y, accB[9]);
        accA[10] = fmaf(zA, p2.z, accA[10]); accB[10] = fmaf(zB, p2.z, accB[10]);
        accA[11] = fmaf(zA, p2.w, accA[11]); accB[11] = fmaf(zB, p2.w, accB[11]);
        accA[12] = fmaf(zA, p3.x, accA[12]); accB[12] = fmaf(zB, p3.x, accB[12]);
        accA[13] = fmaf(zA, p3.y, accA[13]); accB[13] = fmaf(zB, p3.y, accB[13]);
        accA[14] = fmaf(zA, p3.z, accA[14]); accB[14] = fmaf(zB, p3.z, accB[14]);
        accA[15] = fmaf(zA, p3.w, accA[15]); accB[15] = fmaf(zB, p3.w, accB[15]);
    }

    {
        float m = accA[0];
#pragma unroll
        for (int t = 1; t < NT; t++) m = fmaxf(m, accA[t]);
        float s = 0.0f;
#pragma unroll
        for (int t = 0; t < NT; t++) { accA[t] = __expf(accA[t] - m); s += accA[t]; }
        float inv = 1.0f / s;
        float4* o = (float4*)(g_p + (size_t)node0 * NT);
        o[0] = make_float4(accA[0]*inv, accA[1]*inv, accA[2]*inv, accA[3]*inv);
        o[1] = make_float4(accA[4]*inv, accA[5]*inv, accA[6]*inv, accA[7]*inv);
        o[2] = make_float4(accA[8]*inv, accA[9]*inv, accA[10]*inv, accA[11]*inv);
        o[3] = make_float4(accA[12]*inv, accA[13]*inv, accA[14]*inv, accA[15]*inv);
    }
    if (two) {
        float m = accB[0];
#pragma unroll
        for (int t = 1; t < NT; t++) m = fmaxf(m, accB[t]);
        float s = 0.0f;
#pragma unroll
        for (int t = 0; t < NT; t++) { accB[t] = __expf(accB[t] - m); s += accB[t]; }
        float inv = 1.0f / s;
        float4* o = (float4*)(g_p + (size_t)(node0 + 1) * NT);
        o[0] = make_float4(accB[0]*inv, accB[1]*inv, accB[2]*inv, accB[3]*inv);
        o[1] = make_float4(accB[4]*inv, accB[5]*inv, accB[6]*inv, accB[7]*inv);
        o[2] = make_float4(accB[8]*inv, accB[9]*inv, accB[10]*inv, accB[11]*inv);
        o[3] = make_float4(accB[12]*inv, accB[13]*inv, accB[14]*inv, accB[15]*inv);
    }
}

// ---------------------------------------------------------------------------
// Scatter: msum[dst] += p[src].  SIXTEEN lanes per edge, one scalar RED per
// lane -> each RED instruction covers 2 full edges with contiguous 64B rows
// (2 sectors/edge instead of 8). Degree atomics eliminated entirely:
// deg[d] == sum_t msum[d][t] since each softmax row of p sums to 1.
// ---------------------------------------------------------------------------
__global__ void k_scatter(const void* __restrict__ srcv,
                          const void* __restrict__ dstv,
                          int E, int n) {
    int gid = blockIdx.x * blockDim.x + threadIdx.x;
    int e = gid >> 4;           // edge index (2 edges per warp)
    if (e >= E) return;
    int t = gid & 15;           // type index

    int s, d;
    if (g_idx64) {
        s = (int)((const long long*)srcv)[e];   // 16-lane broadcast
        d = (int)((const long long*)dstv)[e];
    } else {
        s = ((const int*)srcv)[e];
        d = ((const int*)dstv)[e];
    }
    s = min(max(s, 0), n - 1);
    d = min(max(d, 0), n - 1);

    float v = __ldg(g_p + (size_t)s * NT + t);  // 16 consecutive 4B = 2 sectors
    atomicAdd(g_msum + (size_t)d * NT + t, v);  // contiguous 64B per edge
}

// ---------------------------------------------------------------------------
// out = relu((msum/max(deg,1)) @ Wf + bf)
// deg reconstructed as the row-sum of msum (softmax rows of p sum to 1).
// j = tid&127 is loop-invariant (stride multiple of 128): the 16 weights for
// this column live in REGISTERS. No smem, no bank conflicts.
// ---------------------------------------------------------------------------
__global__ void __launch_bounds__(256) k_final(
        const float* __restrict__ Wf,
        const float* __restrict__ bf,
        float* __restrict__ out,
        int n) {
    int j = threadIdx.x & 127;
    float w[NT];
#pragma unroll
    for (int t = 0; t < NT; t++) w[t] = Wf[t * OD + j];   // coalesced, L1-hot
    float bj = bf[j];

    int total  = n * OD;
    int stride = gridDim.x * blockDim.x;   // 3200*256 multiple of 128
    for (int gid = blockIdx.x * blockDim.x + threadIdx.x; gid < total; gid += stride) {
        int node = gid >> 7;

        const float4* ms = (const float4*)(g_msum + (size_t)node * NT);
        float4 m0 = ms[0], m1 = ms[1], m2 = ms[2], m3 = ms[3];

        // degree = row sum (p rows sum to 1)
        float dg = ((m0.x + m0.y) + (m0.z + m0.w))
                 + ((m1.x + m1.y) + (m1.z + m1.w))
                 + ((m2.x + m2.y) + (m2.z + m2.w))
                 + ((m3.x + m3.y) + (m3.z + m3.w));
        float invd = 1.0f / fmaxf(nearbyintf(dg), 1.0f);

        float acc = 0.0f;
        acc = fmaf(m0.x, w[0],  acc); acc = fmaf(m0.y, w[1],  acc);
        acc = fmaf(m0.z, w[2],  acc); acc = fmaf(m0.w, w[3],  acc);
        acc = fmaf(m1.x, w[4],  acc); acc = fmaf(m1.y, w[5],  acc);
        acc = fmaf(m1.z, w[6],  acc); acc = fmaf(m1.w, w[7],  acc);
        acc = fmaf(m2.x, w[8],  acc); acc = fmaf(m2.y, w[9],  acc);
        acc = fmaf(m2.z, w[10], acc); acc = fmaf(m2.w, w[11], acc);
        acc = fmaf(m3.x, w[12], acc); acc = fmaf(m3.y, w[13], acc);
        acc = fmaf(m3.z, w[14], acc); acc = fmaf(m3.w, w[15], acc);

        acc = fmaf(invd, acc, bj);
        out[gid] = fmaxf(acc, 0.0f);
    }
}

// ---------------------------------------------------------------------------
// Inputs (metadata order): r, src, dst, W1, b1, Wp, bp, Wf, bf
// ---------------------------------------------------------------------------
extern "C" void kernel_launch(void* const* d_in, const int* in_sizes, int n_in,
                              void* d_out, int out_size) {
    const float* r   = (const float*)d_in[0];
    const void*  src = d_in[1];
    const void*  dst = d_in[2];
    const float* W1  = (const float*)d_in[3];
    const float* b1  = (const float*)d_in[4];
    const float* Wp  = (const float*)d_in[5];
    const float* bp  = (const float*)d_in[6];
    const float* Wf  = (const float*)d_in[7];
    const float* bf  = (const float*)d_in[8];
    float*       out = (float*)d_out;

    int n = in_sizes[0] / NT;   // N nodes
    int E = in_sizes[1];        // edges
    if (n > N_MAX) n = N_MAX;

    k_detect<<<1, 32>>>(src, E);
    {
        int tot = n * NT;
        k_zero<<<(tot + 255) / 256, 256>>>(n);
    }
    k_compute_p<<<((n + 1) / 2 + 127) / 128, 128>>>(r, W1, b1, Wp, bp, n);
    {
        long long threads = (long long)E * 16;
        int blocks = (int)((threads + 255) / 256);
        k_scatter<<<blocks, 256>>>(src, dst, E, n);
    }
    k_final<<<3200, 256>>>(Wf, bf, out, n);
}

// round 8
// speedup vs baseline: 1.4949x; 1.4949x over previous
#include <cuda_runtime.h>
#include <cstdint>

#define NT 16     // NUM_TYPES
#define OD 128    // OUT_DIM
#define N_MAX 100000

// Scratch (allocation-free rule: __device__ globals). 16B-aligned for float4.
// g_p is stored PERMUTED within each 16-float row: position q*4+j holds
// logical element q+4j. This makes scatter's RED #j hit 16 contiguous bytes
// per edge (1 sector) instead of 16B-strided (2 sectors).
__device__ __align__(16) float g_p[N_MAX * NT];
__device__ __align__(16) float g_msum[N_MAX * NT];   // natural layout
__device__ int g_idx64;   // 1 if indices are int64, 0 if int32

// ---------------------------------------------------------------------------
// Detect index width. int32 data misread as int64 gives values >= 2^32 with
// overwhelming probability (hi half would be a random node id, rarely 0).
// ---------------------------------------------------------------------------
__global__ void k_detect(const void* __restrict__ src, int E) {
    if (blockIdx.x == 0 && threadIdx.x == 0) {
        const unsigned long long* p = (const unsigned long long*)src;
        int is64 = 1;
        int lim = (E / 2 < 16) ? E / 2 : 16;
        for (int i = 0; i < lim; i++) {
            if (p[i] > 0x7FFFFFFFULL) is64 = 0;
        }
        g_idx64 = is64;
    }
}

// ---------------------------------------------------------------------------
// Zero msum
// ---------------------------------------------------------------------------
__global__ void k_zero(int n) {
    int i = blockIdx.x * blockDim.x + threadIdx.x;
    if (i < n * NT) g_msum[i] = 0.0f;
}

// ---------------------------------------------------------------------------
// p = softmax(relu(r@W1+b1) @ Wp + bp)   TWO nodes per thread
// Output stored in the permuted layout (see g_p comment): float4 #q of a row
// is {p[q], p[q+4], p[q+8], p[q+12]}.
// ---------------------------------------------------------------------------
__global__ void __launch_bounds__(128) k_compute_p(
        const float* __restrict__ r,
        const float* __restrict__ W1,
        const float* __restrict__ b1,
        const float* __restrict__ Wp,
        const float* __restrict__ bp,
        int n) {
    __shared__ float sW1t[OD * NT];  // [j*16 + k] = W1[k*128 + j]
    __shared__ float sWp [OD * NT];  // [j*16 + t] = Wp[j*16 + t]
    __shared__ float sb1 [OD];
    __shared__ float sbp [NT];

    for (int i = threadIdx.x; i < OD * NT; i += blockDim.x) {
        int j = i >> 4, k = i & 15;
        sW1t[i] = W1[k * OD + j];
        sWp[i]  = Wp[i];
    }
    for (int i = threadIdx.x; i < OD; i += blockDim.x) sb1[i] = b1[i];
    if (threadIdx.x < NT) sbp[threadIdx.x] = bp[threadIdx.x];
    __syncthreads();

    int node0 = (blockIdx.x * blockDim.x + threadIdx.x) * 2;
    if (node0 >= n) return;
    bool two = (node0 + 1 < n);

    const float4* rp0 = (const float4*)(r + (size_t)node0 * NT);
    float4 a0 = rp0[0], a1 = rp0[1], a2 = rp0[2], a3 = rp0[3];
    float4 b0, b1v, b2, b3;
    if (two) {
        const float4* rp1 = (const float4*)(r + (size_t)(node0 + 1) * NT);
        b0 = rp1[0]; b1v = rp1[1]; b2 = rp1[2]; b3 = rp1[3];
    } else {
        b0 = b1v = b2 = b3 = make_float4(0.f, 0.f, 0.f, 0.f);
    }

    float accA[NT], accB[NT];
#pragma unroll
    for (int t = 0; t < NT; t++) { accA[t] = sbp[t]; accB[t] = sbp[t]; }

    const float4* w1t4 = (const float4*)sW1t;
    const float4* wp4  = (const float4*)sWp;

#pragma unroll 2
    for (int j = 0; j < OD; j++) {
        float4 wa = w1t4[j * 4 + 0];
        float4 wb = w1t4[j * 4 + 1];
        float4 wc = w1t4[j * 4 + 2];
        float4 wd = w1t4[j * 4 + 3];
        float bj = sb1[j];

        float zA = bj, zB = bj;
        zA = fmaf(a0.x, wa.x, zA); zA = fmaf(a0.y, wa.y, zA);
        zA = fmaf(a0.z, wa.z, zA); zA = fmaf(a0.w, wa.w, zA);
        zA = fmaf(a1.x, wb.x, zA); zA = fmaf(a1.y, wb.y, zA);
        zA = fmaf(a1.z, wb.z, zA); zA = fmaf(a1.w, wb.w, zA);
        zA = fmaf(a2.x, wc.x, zA); zA = fmaf(a2.y, wc.y, zA);
        zA = fmaf(a2.z, wc.z, zA); zA = fmaf(a2.w, wc.w, zA);
        zA = fmaf(a3.x, wd.x, zA); zA = fmaf(a3.y, wd.y, zA);
        zA = fmaf(a3.z, wd.z, zA); zA = fmaf(a3.w, wd.w, zA);
        zA = fmaxf(zA, 0.0f);

        zB = fmaf(b0.x, wa.x, zB); zB = fmaf(b0.y, wa.y, zB);
        zB = fmaf(b0.z, wa.z, zB); zB = fmaf(b0.w, wa.w, zB);
        zB = fmaf(b1v.x, wb.x, zB); zB = fmaf(b1v.y, wb.y, zB);
        zB = fmaf(b1v.z, wb.z, zB); zB = fmaf(b1v.w, wb.w, zB);
        zB = fmaf(b2.x, wc.x, zB); zB = fmaf(b2.y, wc.y, zB);
        zB = fmaf(b2.z, wc.z, zB); zB = fmaf(b2.w, wc.w, zB);
        zB = fmaf(b3.x, wd.x, zB); zB = fmaf(b3.y, wd.y, zB);
        zB = fmaf(b3.z, wd.z, zB); zB = fmaf(b3.w, wd.w, zB);
        zB = fmaxf(zB, 0.0f);

        float4 p0 = wp4[j * 4 + 0];
        float4 p1 = wp4[j * 4 + 1];
        float4 p2 = wp4[j * 4 + 2];
        float4 p3 = wp4[j * 4 + 3];
        accA[0]  = fmaf(zA, p0.x, accA[0]);  accB[0]  = fmaf(zB, p0.x, accB[0]);
        accA[1]  = fmaf(zA, p0.y, accA[1]);  accB[1]  = fmaf(zB, p0.y, accB[1]);
        accA[2]  = fmaf(zA, p0.z, accA[2]);  accB[2]  = fmaf(zB, p0.z, accB[2]);
        accA[3]  = fmaf(zA, p0.w, accA[3]);  accB[3]  = fmaf(zB, p0.w, accB[3]);
        accA[4]  = fmaf(zA, p1.x, accA[4]);  accB[4]  = fmaf(zB, p1.x, accB[4]);
        accA[5]  = fmaf(zA, p1.y, accA[5]);  accB[5]  = fmaf(zB, p1.y, accB[5]);
        accA[6]  = fmaf(zA, p1.z, accA[6]);  accB[6]  = fmaf(zB, p1.z, accB[6]);
        accA[7]  = fmaf(zA, p1.w, accA[7]);  accB[7]  = fmaf(zB, p1.w, accB[7]);
        accA[8]  = fmaf(zA, p2.x, accA[8]);  accB[8]  = fmaf(zB, p2.x, accB[8]);
        accA[9]  = fmaf(zA, p2.y, accA[9]);  accB[9]  = fmaf(zB, p2.y, accB[9]);
        accA[10] = fmaf(zA, p2.z, accA[10]); accB[10] = fmaf(zB, p2.z, accB[10]);
        accA[11] = fmaf(zA, p2.w, accA[11]); accB[11] = fmaf(zB, p2.w, accB[11]);
        accA[12] = fmaf(zA, p3.x, accA[12]); accB[12] = fmaf(zB, p3.x, accB[12]);
        accA[13] = fmaf(zA, p3.y, accA[13]); accB[13] = fmaf(zB, p3.y, accB[13]);
        accA[14] = fmaf(zA, p3.z, accA[14]); accB[14] = fmaf(zB, p3.z, accB[14]);
        accA[15] = fmaf(zA, p3.w, accA[15]); accB[15] = fmaf(zB, p3.w, accB[15]);
    }

    {
        float m = accA[0];
#pragma unroll
        for (int t = 1; t < NT; t++) m = fmaxf(m, accA[t]);
        float s = 0.0f;
#pragma unroll
        for (int t = 0; t < NT; t++) { accA[t] = __expf(accA[t] - m); s += accA[t]; }
        float inv = 1.0f / s;
        float4* o = (float4*)(g_p + (size_t)node0 * NT);
        // PERMUTED store: float4 #q = {p[q], p[q+4], p[q+8], p[q+12]}
        o[0] = make_float4(accA[0]*inv, accA[4]*inv, accA[8]*inv,  accA[12]*inv);
        o[1] = make_float4(accA[1]*inv, accA[5]*inv, accA[9]*inv,  accA[13]*inv);
        o[2] = make_float4(accA[2]*inv, accA[6]*inv, accA[10]*inv, accA[14]*inv);
        o[3] = make_float4(accA[3]*inv, accA[7]*inv, accA[11]*inv, accA[15]*inv);
    }
    if (two) {
        float m = accB[0];
#pragma unroll
        for (int t = 1; t < NT; t++) m = fmaxf(m, accB[t]);
        float s = 0.0f;
#pragma unroll
        for (int t = 0; t < NT; t++) { accB[t] = __expf(accB[t] - m); s += accB[t]; }
        float inv = 1.0f / s;
        float4* o = (float4*)(g_p + (size_t)(node0 + 1) * NT);
        o[0] = make_float4(accB[0]*inv, accB[4]*inv, accB[8]*inv,  accB[12]*inv);
        o[1] = make_float4(accB[1]*inv, accB[5]*inv, accB[9]*inv,  accB[13]*inv);
        o[2] = make_float4(accB[2]*inv, accB[6]*inv, accB[10]*inv, accB[14]*inv);
        o[3] = make_float4(accB[3]*inv, accB[7]*inv, accB[11]*inv, accB[15]*inv);
    }
}

// ---------------------------------------------------------------------------
// Scatter: msum[dst] += p[src].  4 lanes per edge (R6 layout, measured best).
// Lane q loads permuted float4 = {p[q], p[q+4], p[q+8], p[q+12]} (contiguous
// 16B) and issues 4 scalar REDs to NATURAL msum positions q+4j. RED #j across
// an edge's 4 lanes then covers d*64 + j*16 + q*4 -> 16 CONTIGUOUS bytes
// = 1 sector/edge/RED (was 2). No degree atomics (row-sum trick).
// ---------------------------------------------------------------------------
__global__ void k_scatter(const void* __restrict__ srcv,
                          const void* __restrict__ dstv,
                          int E, int n) {
    int gid = blockIdx.x * blockDim.x + threadIdx.x;
    int e = gid >> 2;
    if (e >= E) return;
    int q = gid & 3;

    int s, d;
    if (g_idx64) {
        s = (int)((const long long*)srcv)[e];
        d = (int)((const long long*)dstv)[e];
    } else {
        s = ((const int*)srcv)[e];
        d = ((const int*)dstv)[e];
    }
    s = min(max(s, 0), n - 1);
    d = min(max(d, 0), n - 1);

    const float4 v = __ldg((const float4*)(g_p + (size_t)s * NT + q * 4));
    float* row = g_msum + (size_t)d * NT + q;
    atomicAdd(row + 0,  v.x);   // element q
    atomicAdd(row + 4,  v.y);   // element q+4
    atomicAdd(row + 8,  v.z);   // element q+8
    atomicAdd(row + 12, v.w);   // element q+12
}

// ---------------------------------------------------------------------------
// out = relu((msum/max(deg,1)) @ Wf + bf)
// deg reconstructed as the row-sum of msum (softmax rows of p sum to 1).
// j = tid&127 is loop-invariant: the 16 weights live in REGISTERS.
// ---------------------------------------------------------------------------
__global__ void __launch_bounds__(256) k_final(
        const float* __restrict__ Wf,
        const float* __restrict__ bf,
        float* __restrict__ out,
        int n) {
    int j = threadIdx.x & 127;
    float w[NT];
#pragma unroll
    for (int t = 0; t < NT; t++) w[t] = Wf[t * OD + j];   // coalesced, L1-hot
    float bj = bf[j];

    int total  = n * OD;
    int stride = gridDim.x * blockDim.x;   // 3200*256 multiple of 128
    for (int gid = blockIdx.x * blockDim.x + threadIdx.x; gid < total; gid += stride) {
        int node = gid >> 7;

        const float4* ms = (const float4*)(g_msum + (size_t)node * NT);
        float4 m0 = ms[0], m1 = ms[1], m2 = ms[2], m3 = ms[3];

        // degree = row sum (p rows sum to 1)
        float dg = ((m0.x + m0.y) + (m0.z + m0.w))
                 + ((m1.x + m1.y) + (m1.z + m1.w))
                 + ((m2.x + m2.y) + (m2.z + m2.w))
                 + ((m3.x + m3.y) + (m3.z + m3.w));
        float invd = 1.0f / fmaxf(nearbyintf(dg), 1.0f);

        float acc = 0.0f;
        acc = fmaf(m0.x, w[0],  acc); acc = fmaf(m0.y, w[1],  acc);
        acc = fmaf(m0.z, w[2],  acc); acc = fmaf(m0.w, w[3],  acc);
        acc = fmaf(m1.x, w[4],  acc); acc = fmaf(m1.y, w[5],  acc);
        acc = fmaf(m1.z, w[6],  acc); acc = fmaf(m1.w, w[7],  acc);
        acc = fmaf(m2.x, w[8],  acc); acc = fmaf(m2.y, w[9],  acc);
        acc = fmaf(m2.z, w[10], acc); acc = fmaf(m2.w, w[11], acc);
        acc = fmaf(m3.x, w[12], acc); acc = fmaf(m3.y, w[13], acc);
        acc = fmaf(m3.z, w[14], acc); acc = fmaf(m3.w, w[15], acc);

        acc = fmaf(invd, acc, bj);
        out[gid] = fmaxf(acc, 0.0f);
    }
}

// ---------------------------------------------------------------------------
// Inputs (metadata order): r, src, dst, W1, b1, Wp, bp, Wf, bf
// ---------------------------------------------------------------------------
extern "C" void kernel_launch(void* const* d_in, const int* in_sizes, int n_in,
                              void* d_out, int out_size) {
    const float* r   = (const float*)d_in[0];
    const void*  src = d_in[1];
    const void*  dst = d_in[2];
    const float* W1  = (const float*)d_in[3];
    const float* b1  = (const float*)d_in[4];
    const float* Wp  = (const float*)d_in[5];
    const float* bp  = (const float*)d_in[6];
    const float* Wf  = (const float*)d_in[7];
    const float* bf  = (const float*)d_in[8];
    float*       out = (float*)d_out;

    int n = in_sizes[0] / NT;   // N nodes
    int E = in_sizes[1];        // edges
    if (n > N_MAX) n = N_MAX;

    k_detect<<<1, 32>>>(src, E);
    {
        int tot = n * NT;
        k_zero<<<(tot + 255) / 256, 256>>>(n);
    }
    k_compute_p<<<((n + 1) / 2 + 127) / 128, 128>>>(r, W1, b1, Wp, bp, n);
    {
        long long threads = (long long)E * 4;
        int blocks = (int)((threads + 255) / 256);
        k_scatter<<<blocks, 256>>>(src, dst, E, n);
    }
    k_final<<<3200, 256>>>(Wf, bf, out, n);
}